// round 5
// baseline (speedup 1.0000x reference)
#include <cuda_runtime.h>
#include <cuda_fp16.h>

// Problem constants
#define BB 8192
#define NN 4
#define CC 1024
#define HH 16
#define DD 64
#define PP 4
#define MTOK (BB*NN)          // 32768
#define SCALE_F 0.125f        // D^-0.5

// ---------------- scratch (static device globals; no allocation) -------------
__device__ __half g_xh[MTOK * CC];              // x in half           (67 MB)
__device__ __half g_wqkvT[3 * CC * CC];         // W_qkv^T [n=3072][k=1024]
__device__ __half g_wprojh[CC * CC];            // W_proj  [n=1024][k=1024] (already k-contig)
__device__ __half g_qkv[MTOK * 3 * CC];         // qkv intermediate    (201 MB)
__device__ __half g_y[MTOK * CC];               // pre-proj heads out  (67 MB)

// ---------------- converts ---------------------------------------------------
__global__ void cvt_x_kernel(const float* __restrict__ x) {
    int i = blockIdx.x * blockDim.x + threadIdx.x;    // over MTOK*CC/4
    float4 v = ((const float4*)x)[i];
    __half2* o = (__half2*)g_xh;
    o[2 * i + 0] = __floats2half2_rn(v.x, v.y);
    o[2 * i + 1] = __floats2half2_rn(v.z, v.w);
}

// W_qkv is [K=1024][N=3072]; produce half [N][K] (k-contiguous) via smem tile transpose
__global__ void cvt_wqkv_kernel(const float* __restrict__ w) {
    __shared__ float t[32][33];
    int bn = blockIdx.x * 32;   // n tile
    int bk = blockIdx.y * 32;   // k tile
    for (int r = threadIdx.y; r < 32; r += 8)
        t[r][threadIdx.x] = w[(bk + r) * 3072 + bn + threadIdx.x];
    __syncthreads();
    for (int r = threadIdx.y; r < 32; r += 8)
        g_wqkvT[(bn + r) * 1024 + bk + threadIdx.x] = __float2half_rn(t[threadIdx.x][r]);
}

__global__ void cvt_wproj_kernel(const float* __restrict__ w) {
    int i = blockIdx.x * blockDim.x + threadIdx.x;    // over CC*CC
    g_wprojh[i] = __float2half_rn(w[i]);
}

// ---------------- GEMM: C[M,N] = A[M,K] * B^T (B stored [N][K] k-contig) -----
// 128x128 CTA tile, BK=32, 8 warps (2x4), warp tile 64x32, mma.m16n8k16 f16->f32
__device__ __forceinline__ void cp16(void* s, const void* g) {
    unsigned sa = (unsigned)__cvta_generic_to_shared(s);
    asm volatile("cp.async.cg.shared.global [%0], [%1], 16;\n" :: "r"(sa), "l"(g));
}

template<bool HALF_OUT>
__global__ __launch_bounds__(256) void gemm_kernel(
    const __half* __restrict__ A, const __half* __restrict__ Bm,
    __half* __restrict__ Ch, float* __restrict__ Cf,
    const float* __restrict__ bias, int N, int K)
{
    __shared__ __half As[2][128][40];
    __shared__ __half Bs[2][128][40];

    const int tid  = threadIdx.x;
    const int warp = tid >> 5, lane = tid & 31;
    const int wm = (warp >> 2) * 64;       // 0 / 64
    const int wn = (warp & 3) * 32;        // 0..96
    const int g  = lane >> 2, t4 = lane & 3;
    const int bM = blockIdx.y * 128;
    const int bN = blockIdx.x * 128;

    float acc[4][4][4];
    #pragma unroll
    for (int mi = 0; mi < 4; mi++)
        #pragma unroll
        for (int ni = 0; ni < 4; ni++)
            #pragma unroll
            for (int r = 0; r < 4; r++) acc[mi][ni][r] = 0.f;

    const int lr = tid >> 2;               // 0..63
    const int lo = (tid & 3) * 8;          // 0,8,16,24 halves

    auto load_tiles = [&](int s, int kt) {
        int k0 = kt * 32;
        const __half* Ag = A + (long)(bM + lr) * K + k0 + lo;
        cp16(&As[s][lr][lo],       Ag);
        cp16(&As[s][64 + lr][lo],  Ag + (long)64 * K);
        const __half* Bg = Bm + (long)(bN + lr) * K + k0 + lo;
        cp16(&Bs[s][lr][lo],       Bg);
        cp16(&Bs[s][64 + lr][lo],  Bg + (long)64 * K);
    };

    const int KT = K / 32;
    load_tiles(0, 0);
    asm volatile("cp.async.commit_group;\n" ::: "memory");

    int buf = 0;
    for (int kt = 0; kt < KT; ++kt) {
        asm volatile("cp.async.wait_group 0;\n" ::: "memory");
        __syncthreads();
        if (kt + 1 < KT) {
            load_tiles(buf ^ 1, kt + 1);
            asm volatile("cp.async.commit_group;\n" ::: "memory");
        }
        #pragma unroll
        for (int ks = 0; ks < 32; ks += 16) {
            unsigned af[4][4], bf[4][2];
            #pragma unroll
            for (int mi = 0; mi < 4; mi++) {
                int row = wm + mi * 16 + g;
                af[mi][0] = *(const unsigned*)&As[buf][row][ks + t4 * 2];
                af[mi][1] = *(const unsigned*)&As[buf][row + 8][ks + t4 * 2];
                af[mi][2] = *(const unsigned*)&As[buf][row][ks + t4 * 2 + 8];
                af[mi][3] = *(const unsigned*)&As[buf][row + 8][ks + t4 * 2 + 8];
            }
            #pragma unroll
            for (int ni = 0; ni < 4; ni++) {
                int col = wn + ni * 8 + g;
                bf[ni][0] = *(const unsigned*)&Bs[buf][col][ks + t4 * 2];
                bf[ni][1] = *(const unsigned*)&Bs[buf][col][ks + t4 * 2 + 8];
            }
            #pragma unroll
            for (int mi = 0; mi < 4; mi++)
                #pragma unroll
                for (int ni = 0; ni < 4; ni++)
                    asm volatile(
                        "mma.sync.aligned.m16n8k16.row.col.f32.f16.f16.f32 "
                        "{%0,%1,%2,%3}, {%4,%5,%6,%7}, {%8,%9}, {%0,%1,%2,%3};\n"
                        : "+f"(acc[mi][ni][0]), "+f"(acc[mi][ni][1]),
                          "+f"(acc[mi][ni][2]), "+f"(acc[mi][ni][3])
                        : "r"(af[mi][0]), "r"(af[mi][1]), "r"(af[mi][2]), "r"(af[mi][3]),
                          "r"(bf[ni][0]), "r"(bf[ni][1]));
        }
        __syncthreads();
        buf ^= 1;
    }

    #pragma unroll
    for (int mi = 0; mi < 4; mi++) {
        int row = bM + wm + mi * 16 + g;
        #pragma unroll
        for (int ni = 0; ni < 4; ni++) {
            int col = bN + wn + ni * 8 + t4 * 2;
            if (HALF_OUT) {
                *(__half2*)&Ch[(long)row * N + col] =
                    __floats2half2_rn(acc[mi][ni][0], acc[mi][ni][1]);
                *(__half2*)&Ch[(long)(row + 8) * N + col] =
                    __floats2half2_rn(acc[mi][ni][2], acc[mi][ni][3]);
            } else {
                float b0 = bias[col], b1 = bias[col + 1];
                float2 v0 = make_float2(acc[mi][ni][0] + b0, acc[mi][ni][1] + b1);
                float2 v1 = make_float2(acc[mi][ni][2] + b0, acc[mi][ni][3] + b1);
                *(float2*)&Cf[(long)row * N + col] = v0;
                *(float2*)&Cf[(long)(row + 8) * N + col] = v1;
            }
        }
    }
}

// ---------------- middle stage: per-batch Linformer attention ----------------
// qkv row layout: g_qkv[(b*4+n)*3072 + s*1024 + h*64 + d], s=0:q 1:k 2:v
__global__ __launch_bounds__(128) void mid_kernel(
    const __half* __restrict__ qkv_all, __half* __restrict__ y,
    const float* __restrict__ W_E, const float* __restrict__ W_F,
    float* __restrict__ attn_out)
{
    __shared__ __half buf[4 * 1024];          // one of {k, v} staged
    __shared__ float klow[16][4][64];
    __shared__ float vlow[16][4][64];
    __shared__ float wE[4][4], wF[4][4];

    const int b = blockIdx.x, t = threadIdx.x;
    const __half* qkv = qkv_all + (long)b * 4 * 3072;

    if (t < 16) { wE[t >> 2][t & 3] = W_E[t]; wF[t >> 2][t & 3] = W_F[t]; }

    // stage K rows (s=1)
    for (int i = t; i < 512; i += 128) {
        int n = i >> 7, c8 = (i & 127) << 3;
        *(uint4*)&buf[n * 1024 + c8] = *(const uint4*)&qkv[n * 3072 + 1024 + c8];
    }
    __syncthreads();

    // klow[h][p][d] = sum_n wE[p][n] * k[n][h*64+d]
    for (int i = t; i < 1024; i += 128) {
        int h = i >> 6, d = i & 63, c = h * 64 + d;
        float k0 = __half2float(buf[c]);
        float k1 = __half2float(buf[1024 + c]);
        float k2 = __half2float(buf[2048 + c]);
        float k3 = __half2float(buf[3072 + c]);
        #pragma unroll
        for (int p = 0; p < 4; p++)
            klow[h][p][d] = wE[p][0] * k0 + wE[p][1] * k1 + wE[p][2] * k2 + wE[p][3] * k3;
    }

    // attn_sel_sig[h][g] = sigmoid( SCALE * q[n=1,h,:] . k[n=2,g,:] )
    for (int i = t; i < 256; i += 128) {
        int h = i >> 4, gg = i & 15;
        const __half* qrow = qkv + 1 * 3072 + h * 64;
        const __half* krow = &buf[2048 + gg * 64];
        float s = 0.f;
        #pragma unroll
        for (int d = 0; d < 64; d++)
            s += __half2float(qrow[d]) * __half2float(krow[d]);
        s *= SCALE_F;
        attn_out[b * 256 + i] = 1.f / (1.f + expf(-s));
    }
    __syncthreads();

    // stage V rows (s=2)
    for (int i = t; i < 512; i += 128) {
        int n = i >> 7, c8 = (i & 127) << 3;
        *(uint4*)&buf[n * 1024 + c8] = *(const uint4*)&qkv[n * 3072 + 2048 + c8];
    }
    __syncthreads();

    for (int i = t; i < 1024; i += 128) {
        int h = i >> 6, d = i & 63, c = h * 64 + d;
        float v0 = __half2float(buf[c]);
        float v1 = __half2float(buf[1024 + c]);
        float v2 = __half2float(buf[2048 + c]);
        float v3 = __half2float(buf[3072 + c]);
        #pragma unroll
        for (int p = 0; p < 4; p++)
            vlow[h][p][d] = wF[p][0] * v0 + wF[p][1] * v1 + wF[p][2] * v2 + wF[p][3] * v3;
    }
    __syncthreads();

    // attn softmax over P=4 and Y = attn @ vlow
    if (t < 64) {
        int h = t >> 2, n = t & 3;
        const __half* qrow = qkv + n * 3072 + h * 64;
        float l0 = 0, l1 = 0, l2 = 0, l3 = 0;
        #pragma unroll
        for (int d = 0; d < 64; d++) {
            float qv = __half2float(qrow[d]);
            l0 += qv * klow[h][0][d];
            l1 += qv * klow[h][1][d];
            l2 += qv * klow[h][2][d];
            l3 += qv * klow[h][3][d];
        }
        l0 *= SCALE_F; l1 *= SCALE_F; l2 *= SCALE_F; l3 *= SCALE_F;
        float m = fmaxf(fmaxf(l0, l1), fmaxf(l2, l3));
        float e0 = expf(l0 - m), e1 = expf(l1 - m), e2 = expf(l2 - m), e3 = expf(l3 - m);
        float inv = 1.f / (e0 + e1 + e2 + e3);
        e0 *= inv; e1 *= inv; e2 *= inv; e3 *= inv;
        __half* yrow = y + (long)(b * 4 + n) * 1024 + h * 64;
        #pragma unroll
        for (int d = 0; d < 64; d += 2) {
            float o0 = e0 * vlow[h][0][d] + e1 * vlow[h][1][d] + e2 * vlow[h][2][d] + e3 * vlow[h][3][d];
            float o1 = e0 * vlow[h][0][d + 1] + e1 * vlow[h][1][d + 1] + e2 * vlow[h][2][d + 1] + e3 * vlow[h][3][d + 1];
            *(__half2*)&yrow[d] = __floats2half2_rn(o0, o1);
        }
    }
}

// ---------------- launch -----------------------------------------------------
extern "C" void kernel_launch(void* const* d_in, const int* in_sizes, int n_in,
                              void* d_out, int out_size)
{
    const float* x     = (const float*)d_in[0];
    const float* Wqkv  = (const float*)d_in[1];
    const float* Wproj = (const float*)d_in[2];
    const float* bproj = (const float*)d_in[3];
    const float* WE    = (const float*)d_in[4];
    const float* WF    = (const float*)d_in[5];
    float* out = (float*)d_out;

    void *p_xh, *p_wq, *p_wp, *p_qkv, *p_y;
    cudaGetSymbolAddress(&p_xh,  g_xh);
    cudaGetSymbolAddress(&p_wq,  g_wqkvT);
    cudaGetSymbolAddress(&p_wp,  g_wprojh);
    cudaGetSymbolAddress(&p_qkv, g_qkv);
    cudaGetSymbolAddress(&p_y,   g_y);
    const __half* xh   = (const __half*)p_xh;
    const __half* wqT  = (const __half*)p_wq;
    const __half* wph  = (const __half*)p_wp;
    __half* qkv = (__half*)p_qkv;
    __half* y   = (__half*)p_y;

    // converts
    cvt_x_kernel<<<MTOK * CC / 4 / 256, 256>>>(x);
    cvt_wqkv_kernel<<<dim3(96, 32), dim3(32, 8)>>>(Wqkv);
    cvt_wproj_kernel<<<CC * CC / 256, 256>>>(Wproj);

    // GEMM1: qkv = x @ W_qkv   (M=32768, N=3072, K=1024) -> half
    gemm_kernel<true><<<dim3(3072 / 128, MTOK / 128), 256>>>(
        xh, wqT, qkv, nullptr, nullptr, 3072, 1024);

    // middle attention per batch
    mid_kernel<<<BB, 128>>>(qkv, y, WE, WF, out + (long)MTOK * CC);

    // GEMM2: out = Y @ W_proj^T + b   (M=32768, N=1024, K=1024) -> fp32 into d_out
    gemm_kernel<false><<<dim3(1024 / 128, MTOK / 128), 256>>>(
        y, wph, nullptr, out, bproj, 1024, 1024);
}

// round 8
// speedup vs baseline: 1.0583x; 1.0583x over previous
#include <cuda_runtime.h>
#include <cuda_fp16.h>

// Problem constants
#define BB 8192
#define NN 4
#define CC 1024
#define HH 16
#define DD 64
#define PP 4
#define MTOK (BB*NN)          // 32768
#define SCALE_F 0.125f        // D^-0.5

// ---------------- scratch (static device globals; no allocation) -------------
__device__ __half g_xh[MTOK * CC];              // x in half           (67 MB)
__device__ __half g_wqkvT[3 * CC * CC];         // W_qkv^T [n=3072][k=1024]
__device__ __half g_wprojh[CC * CC];            // W_proj  [n=1024][k=1024] (already k-contig)
__device__ __half g_qkv[MTOK * 3 * CC];         // qkv intermediate    (201 MB)
__device__ __half g_y[MTOK * CC];               // pre-proj heads out  (67 MB)

// ---------------- converts ---------------------------------------------------
__global__ void cvt_x_kernel(const float* __restrict__ x) {
    int i = blockIdx.x * blockDim.x + threadIdx.x;    // over MTOK*CC/4
    float4 v = ((const float4*)x)[i];
    __half2* o = (__half2*)g_xh;
    o[2 * i + 0] = __floats2half2_rn(v.x, v.y);
    o[2 * i + 1] = __floats2half2_rn(v.z, v.w);
}

// W_qkv is [K=1024][N=3072]; produce half [N][K] (k-contiguous) via smem tile transpose
__global__ void cvt_wqkv_kernel(const float* __restrict__ w) {
    __shared__ float t[32][33];
    int bn = blockIdx.x * 32;   // n tile
    int bk = blockIdx.y * 32;   // k tile
    for (int r = threadIdx.y; r < 32; r += 8)
        t[r][threadIdx.x] = w[(bk + r) * 3072 + bn + threadIdx.x];
    __syncthreads();
    for (int r = threadIdx.y; r < 32; r += 8)
        g_wqkvT[(bn + r) * 1024 + bk + threadIdx.x] = __float2half_rn(t[threadIdx.x][r]);
}

__global__ void cvt_wproj_kernel(const float* __restrict__ w) {
    int i = blockIdx.x * blockDim.x + threadIdx.x;    // over CC*CC
    g_wprojh[i] = __float2half_rn(w[i]);
}

// ---------------- GEMM: C[M,N] = A[M,K] * B^T (B stored [N][K] k-contig) -----
// 128x128 CTA tile, BK=32, 8 warps (2x4), warp tile 64x32, mma.m16n8k16 f16->f32
// Fragments loaded via ldmatrix.x4 (6 LDSM per warp per k16 instead of 24 LDS.32)
__device__ __forceinline__ void cp16(void* s, const void* g) {
    unsigned sa = (unsigned)__cvta_generic_to_shared(s);
    asm volatile("cp.async.cg.shared.global [%0], [%1], 16;\n" :: "r"(sa), "l"(g));
}

__device__ __forceinline__ void ldsm4(unsigned& r0, unsigned& r1, unsigned& r2, unsigned& r3,
                                      const void* p) {
    unsigned sa = (unsigned)__cvta_generic_to_shared(p);
    asm volatile("ldmatrix.sync.aligned.m8n8.x4.shared.b16 {%0,%1,%2,%3}, [%4];\n"
                 : "=r"(r0), "=r"(r1), "=r"(r2), "=r"(r3) : "r"(sa));
}

template<bool HALF_OUT>
__global__ __launch_bounds__(256, 2) void gemm_kernel(
    const __half* __restrict__ A, const __half* __restrict__ Bm,
    __half* __restrict__ Ch, float* __restrict__ Cf,
    const float* __restrict__ bias, int N, int K)
{
    __shared__ __half As[2][128][40];
    __shared__ __half Bs[2][128][40];

    const int tid  = threadIdx.x;
    const int warp = tid >> 5, lane = tid & 31;
    const int wm = (warp >> 2) * 64;       // 0 / 64
    const int wn = (warp & 3) * 32;        // 0..96
    const int g  = lane >> 2, t4 = lane & 3;
    const int bM = blockIdx.y * 128;
    const int bN = blockIdx.x * 128;

    // ldmatrix lane addressing (verified conflict-free with 40-half row stride)
    // A x4: mat0 rows0-7/kLo, mat1 rows8-15/kLo, mat2 rows0-7/kHi, mat3 rows8-15/kHi
    const int a_row_off = ((lane >> 3) & 1) * 8 + (lane & 7);
    const int a_col_off = (lane >> 4) * 8;
    // B x4: mat0 cols0-7/kLo, mat1 cols0-7/kHi, mat2 cols8-15/kLo, mat3 cols8-15/kHi
    const int b_row_off = ((lane >> 4) & 1) * 8 + (lane & 7);
    const int b_col_off = ((lane >> 3) & 1) * 8;

    float acc[4][4][4];
    #pragma unroll
    for (int mi = 0; mi < 4; mi++)
        #pragma unroll
        for (int ni = 0; ni < 4; ni++)
            #pragma unroll
            for (int r = 0; r < 4; r++) acc[mi][ni][r] = 0.f;

    const int lr = tid >> 2;               // 0..63
    const int lo = (tid & 3) * 8;          // 0,8,16,24 halves

    auto load_tiles = [&](int s, int kt) {
        int k0 = kt * 32;
        const __half* Ag = A + (long)(bM + lr) * K + k0 + lo;
        cp16(&As[s][lr][lo],       Ag);
        cp16(&As[s][64 + lr][lo],  Ag + (long)64 * K);
        const __half* Bg = Bm + (long)(bN + lr) * K + k0 + lo;
        cp16(&Bs[s][lr][lo],       Bg);
        cp16(&Bs[s][64 + lr][lo],  Bg + (long)64 * K);
    };

    const int KT = K / 32;
    load_tiles(0, 0);
    asm volatile("cp.async.commit_group;\n" ::: "memory");

    int buf = 0;
    for (int kt = 0; kt < KT; ++kt) {
        asm volatile("cp.async.wait_group 0;\n" ::: "memory");
        __syncthreads();
        if (kt + 1 < KT) {
            load_tiles(buf ^ 1, kt + 1);
            asm volatile("cp.async.commit_group;\n" ::: "memory");
        }
        #pragma unroll
        for (int ks = 0; ks < 32; ks += 16) {
            unsigned af[4][4], bf[4][2];
            #pragma unroll
            for (int mi = 0; mi < 4; mi++)
                ldsm4(af[mi][0], af[mi][1], af[mi][2], af[mi][3],
                      &As[buf][wm + mi * 16 + a_row_off][ks + a_col_off]);
            #pragma unroll
            for (int j = 0; j < 2; j++)
                ldsm4(bf[2 * j][0], bf[2 * j][1], bf[2 * j + 1][0], bf[2 * j + 1][1],
                      &Bs[buf][wn + j * 16 + b_row_off][ks + b_col_off]);
            #pragma unroll
            for (int mi = 0; mi < 4; mi++)
                #pragma unroll
                for (int ni = 0; ni < 4; ni++)
                    asm volatile(
                        "mma.sync.aligned.m16n8k16.row.col.f32.f16.f16.f32 "
                        "{%0,%1,%2,%3}, {%4,%5,%6,%7}, {%8,%9}, {%0,%1,%2,%3};\n"
                        : "+f"(acc[mi][ni][0]), "+f"(acc[mi][ni][1]),
                          "+f"(acc[mi][ni][2]), "+f"(acc[mi][ni][3])
                        : "r"(af[mi][0]), "r"(af[mi][1]), "r"(af[mi][2]), "r"(af[mi][3]),
                          "r"(bf[ni][0]), "r"(bf[ni][1]));
        }
        __syncthreads();
        buf ^= 1;
    }

    #pragma unroll
    for (int mi = 0; mi < 4; mi++) {
        int row = bM + wm + mi * 16 + g;
        #pragma unroll
        for (int ni = 0; ni < 4; ni++) {
            int col = bN + wn + ni * 8 + t4 * 2;
            if (HALF_OUT) {
                *(__half2*)&Ch[(long)row * N + col] =
                    __floats2half2_rn(acc[mi][ni][0], acc[mi][ni][1]);
                *(__half2*)&Ch[(long)(row + 8) * N + col] =
                    __floats2half2_rn(acc[mi][ni][2], acc[mi][ni][3]);
            } else {
                float b0 = bias[col], b1 = bias[col + 1];
                float2 v0 = make_float2(acc[mi][ni][0] + b0, acc[mi][ni][1] + b1);
                float2 v1 = make_float2(acc[mi][ni][2] + b0, acc[mi][ni][3] + b1);
                *(float2*)&Cf[(long)row * N + col] = v0;
                *(float2*)&Cf[(long)(row + 8) * N + col] = v1;
            }
        }
    }
}

// ---------------- middle stage: per-batch Linformer attention ----------------
// qkv row layout: g_qkv[(b*4+n)*3072 + s*1024 + h*64 + d], s=0:q 1:k 2:v
__global__ __launch_bounds__(128) void mid_kernel(
    const __half* __restrict__ qkv_all, __half* __restrict__ y,
    const float* __restrict__ W_E, const float* __restrict__ W_F,
    float* __restrict__ attn_out)
{
    __shared__ __half buf[4 * 1024];          // one of {k, v} staged
    __shared__ float klow[16][4][64];
    __shared__ float vlow[16][4][64];
    __shared__ float wE[4][4], wF[4][4];

    const int b = blockIdx.x, t = threadIdx.x;
    const __half* qkv = qkv_all + (long)b * 4 * 3072;

    if (t < 16) { wE[t >> 2][t & 3] = W_E[t]; wF[t >> 2][t & 3] = W_F[t]; }

    // stage K rows (s=1)
    for (int i = t; i < 512; i += 128) {
        int n = i >> 7, c8 = (i & 127) << 3;
        *(uint4*)&buf[n * 1024 + c8] = *(const uint4*)&qkv[n * 3072 + 1024 + c8];
    }
    __syncthreads();

    // klow[h][p][d] = sum_n wE[p][n] * k[n][h*64+d]
    for (int i = t; i < 1024; i += 128) {
        int h = i >> 6, d = i & 63, c = h * 64 + d;
        float k0 = __half2float(buf[c]);
        float k1 = __half2float(buf[1024 + c]);
        float k2 = __half2float(buf[2048 + c]);
        float k3 = __half2float(buf[3072 + c]);
        #pragma unroll
        for (int p = 0; p < 4; p++)
            klow[h][p][d] = wE[p][0] * k0 + wE[p][1] * k1 + wE[p][2] * k2 + wE[p][3] * k3;
    }

    // attn_sel_sig[h][g] = sigmoid( SCALE * q[n=1,h,:] . k[n=2,g,:] )
    for (int i = t; i < 256; i += 128) {
        int h = i >> 4, gg = i & 15;
        const __half* qrow = qkv + 1 * 3072 + h * 64;
        const __half* krow = &buf[2048 + gg * 64];
        float s = 0.f;
        #pragma unroll
        for (int d = 0; d < 64; d++)
            s += __half2float(qrow[d]) * __half2float(krow[d]);
        s *= SCALE_F;
        attn_out[b * 256 + i] = 1.f / (1.f + expf(-s));
    }
    __syncthreads();

    // stage V rows (s=2)
    for (int i = t; i < 512; i += 128) {
        int n = i >> 7, c8 = (i & 127) << 3;
        *(uint4*)&buf[n * 1024 + c8] = *(const uint4*)&qkv[n * 3072 + 2048 + c8];
    }
    __syncthreads();

    for (int i = t; i < 1024; i += 128) {
        int h = i >> 6, d = i & 63, c = h * 64 + d;
        float v0 = __half2float(buf[c]);
        float v1 = __half2float(buf[1024 + c]);
        float v2 = __half2float(buf[2048 + c]);
        float v3 = __half2float(buf[3072 + c]);
        #pragma unroll
        for (int p = 0; p < 4; p++)
            vlow[h][p][d] = wF[p][0] * v0 + wF[p][1] * v1 + wF[p][2] * v2 + wF[p][3] * v3;
    }
    __syncthreads();

    // attn softmax over P=4 and Y = attn @ vlow
    if (t < 64) {
        int h = t >> 2, n = t & 3;
        const __half* qrow = qkv + n * 3072 + h * 64;
        float l0 = 0, l1 = 0, l2 = 0, l3 = 0;
        #pragma unroll
        for (int d = 0; d < 64; d++) {
            float qv = __half2float(qrow[d]);
            l0 += qv * klow[h][0][d];
            l1 += qv * klow[h][1][d];
            l2 += qv * klow[h][2][d];
            l3 += qv * klow[h][3][d];
        }
        l0 *= SCALE_F; l1 *= SCALE_F; l2 *= SCALE_F; l3 *= SCALE_F;
        float m = fmaxf(fmaxf(l0, l1), fmaxf(l2, l3));
        float e0 = expf(l0 - m), e1 = expf(l1 - m), e2 = expf(l2 - m), e3 = expf(l3 - m);
        float inv = 1.f / (e0 + e1 + e2 + e3);
        e0 *= inv; e1 *= inv; e2 *= inv; e3 *= inv;
        __half* yrow = y + (long)(b * 4 + n) * 1024 + h * 64;
        #pragma unroll
        for (int d = 0; d < 64; d += 2) {
            float o0 = e0 * vlow[h][0][d] + e1 * vlow[h][1][d] + e2 * vlow[h][2][d] + e3 * vlow[h][3][d];
            float o1 = e0 * vlow[h][0][d + 1] + e1 * vlow[h][1][d + 1] + e2 * vlow[h][2][d + 1] + e3 * vlow[h][3][d + 1];
            *(__half2*)&yrow[d] = __floats2half2_rn(o0, o1);
        }
    }
}

// ---------------- launch -----------------------------------------------------
extern "C" void kernel_launch(void* const* d_in, const int* in_sizes, int n_in,
                              void* d_out, int out_size)
{
    const float* x     = (const float*)d_in[0];
    const float* Wqkv  = (const float*)d_in[1];
    const float* Wproj = (const float*)d_in[2];
    const float* bproj = (const float*)d_in[3];
    const float* WE    = (const float*)d_in[4];
    const float* WF    = (const float*)d_in[5];
    float* out = (float*)d_out;

    void *p_xh, *p_wq, *p_wp, *p_qkv, *p_y;
    cudaGetSymbolAddress(&p_xh,  g_xh);
    cudaGetSymbolAddress(&p_wq,  g_wqkvT);
    cudaGetSymbolAddress(&p_wp,  g_wprojh);
    cudaGetSymbolAddress(&p_qkv, g_qkv);
    cudaGetSymbolAddress(&p_y,   g_y);
    const __half* xh   = (const __half*)p_xh;
    const __half* wqT  = (const __half*)p_wq;
    const __half* wph  = (const __half*)p_wp;
    __half* qkv = (__half*)p_qkv;
    __half* y   = (__half*)p_y;

    // converts
    cvt_x_kernel<<<MTOK * CC / 4 / 256, 256>>>(x);
    cvt_wqkv_kernel<<<dim3(96, 32), dim3(32, 8)>>>(Wqkv);
    cvt_wproj_kernel<<<CC * CC / 256, 256>>>(Wproj);

    // GEMM1: qkv = x @ W_qkv   (M=32768, N=3072, K=1024) -> half
    gemm_kernel<true><<<dim3(3072 / 128, MTOK / 128), 256>>>(
        xh, wqT, qkv, nullptr, nullptr, 3072, 1024);

    // middle attention per batch
    mid_kernel<<<BB, 128>>>(qkv, y, WE, WF, out + (long)MTOK * CC);

    // GEMM2: out = Y @ W_proj^T + b   (M=32768, N=1024, K=1024) -> fp32 into d_out
    gemm_kernel<false><<<dim3(1024 / 128, MTOK / 128), 256>>>(
        y, wph, nullptr, out, bproj, 1024, 1024);
}

// round 16
// speedup vs baseline: 1.1912x; 1.1256x over previous
#include <cuda_runtime.h>
#include <cuda_fp16.h>

// Problem constants
#define BB 8192
#define NN 4
#define CC 1024
#define HH 16
#define DD 64
#define PP 4
#define MTOK (BB*NN)          // 32768
#define SCALE_F 0.125f        // D^-0.5

// ---------------- scratch (static device globals; no allocation) -------------
__device__ __half g_xh[MTOK * CC];              // x in half           (67 MB)
__device__ __half g_wqkvT[3 * CC * CC];         // W_qkv^T [n=3072][k=1024]
__device__ __half g_wprojh[CC * CC];            // W_proj  [n=1024][k=1024]
__device__ __half g_qkv[MTOK * 3 * CC];         // qkv intermediate    (201 MB)
__device__ __half g_y[MTOK * CC];               // pre-proj heads out  (67 MB)

// ---------------- converts ---------------------------------------------------
__global__ void cvt_x_kernel(const float* __restrict__ x) {
    int i = blockIdx.x * blockDim.x + threadIdx.x;    // over MTOK*CC/4
    float4 v = ((const float4*)x)[i];
    __half2* o = (__half2*)g_xh;
    o[2 * i + 0] = __floats2half2_rn(v.x, v.y);
    o[2 * i + 1] = __floats2half2_rn(v.z, v.w);
}

__global__ void cvt_wqkv_kernel(const float* __restrict__ w) {
    __shared__ float t[32][33];
    int bn = blockIdx.x * 32;   // n tile
    int bk = blockIdx.y * 32;   // k tile
    for (int r = threadIdx.y; r < 32; r += 8)
        t[r][threadIdx.x] = w[(bk + r) * 3072 + bn + threadIdx.x];
    __syncthreads();
    for (int r = threadIdx.y; r < 32; r += 8)
        g_wqkvT[(bn + r) * 1024 + bk + threadIdx.x] = __float2half_rn(t[threadIdx.x][r]);
}

__global__ void cvt_wproj_kernel(const float* __restrict__ w) {
    int i = blockIdx.x * blockDim.x + threadIdx.x;    // over CC*CC
    g_wprojh[i] = __float2half_rn(w[i]);
}

// ---------------- GEMM: C[M,N] = A[M,K] * B^T (B stored [N][K] k-contig) -----
// 128x128 CTA tile, BK=32, 8 warps (2x4), warp tile 64x32, mma.m16n8k16 f16->f32
// Fragments via ldmatrix.x4 (6 LDSM per warp per k16)
__device__ __forceinline__ void cp16(void* s, const void* g) {
    unsigned sa = (unsigned)__cvta_generic_to_shared(s);
    asm volatile("cp.async.cg.shared.global [%0], [%1], 16;\n" :: "r"(sa), "l"(g));
}

__device__ __forceinline__ void ldsm4(unsigned& r0, unsigned& r1, unsigned& r2, unsigned& r3,
                                      const void* p) {
    unsigned sa = (unsigned)__cvta_generic_to_shared(p);
    asm volatile("ldmatrix.sync.aligned.m8n8.x4.shared.b16 {%0,%1,%2,%3}, [%4];\n"
                 : "=r"(r0), "=r"(r1), "=r"(r2), "=r"(r3) : "r"(sa));
}

template<bool HALF_OUT>
__global__ __launch_bounds__(256, 2) void gemm_kernel(
    const __half* __restrict__ A, const __half* __restrict__ Bm,
    __half* __restrict__ Ch, float* __restrict__ Cf,
    const float* __restrict__ bias, int N, int K)
{
    __shared__ __half As[2][128][40];
    __shared__ __half Bs[2][128][40];

    const int tid  = threadIdx.x;
    const int warp = tid >> 5, lane = tid & 31;
    const int wm = (warp >> 2) * 64;       // 0 / 64
    const int wn = (warp & 3) * 32;        // 0..96
    const int g  = lane >> 2, t4 = lane & 3;
    const int bM = blockIdx.y * 128;
    const int bN = blockIdx.x * 128;

    // ldmatrix lane addressing (conflict-free with 40-half row stride)
    const int a_row_off = ((lane >> 3) & 1) * 8 + (lane & 7);
    const int a_col_off = (lane >> 4) * 8;
    const int b_row_off = ((lane >> 4) & 1) * 8 + (lane & 7);
    const int b_col_off = ((lane >> 3) & 1) * 8;

    float acc[4][4][4];
    #pragma unroll
    for (int mi = 0; mi < 4; mi++)
        #pragma unroll
        for (int ni = 0; ni < 4; ni++)
            #pragma unroll
            for (int r = 0; r < 4; r++) acc[mi][ni][r] = 0.f;

    const int lr = tid >> 2;               // 0..63
    const int lo = (tid & 3) * 8;          // 0,8,16,24 halves

    auto load_tiles = [&](int s, int kt) {
        int k0 = kt * 32;
        const __half* Ag = A + (long)(bM + lr) * K + k0 + lo;
        cp16(&As[s][lr][lo],       Ag);
        cp16(&As[s][64 + lr][lo],  Ag + (long)64 * K);
        const __half* Bg = Bm + (long)(bN + lr) * K + k0 + lo;
        cp16(&Bs[s][lr][lo],       Bg);
        cp16(&Bs[s][64 + lr][lo],  Bg + (long)64 * K);
    };

    const int KT = K / 32;
    load_tiles(0, 0);
    asm volatile("cp.async.commit_group;\n" ::: "memory");

    int buf = 0;
    for (int kt = 0; kt < KT; ++kt) {
        asm volatile("cp.async.wait_group 0;\n" ::: "memory");
        __syncthreads();
        if (kt + 1 < KT) {
            load_tiles(buf ^ 1, kt + 1);
            asm volatile("cp.async.commit_group;\n" ::: "memory");
        }
        #pragma unroll
        for (int ks = 0; ks < 32; ks += 16) {
            unsigned af[4][4], bf[4][2];
            #pragma unroll
            for (int mi = 0; mi < 4; mi++)
                ldsm4(af[mi][0], af[mi][1], af[mi][2], af[mi][3],
                      &As[buf][wm + mi * 16 + a_row_off][ks + a_col_off]);
            #pragma unroll
            for (int j = 0; j < 2; j++)
                ldsm4(bf[2 * j][0], bf[2 * j][1], bf[2 * j + 1][0], bf[2 * j + 1][1],
                      &Bs[buf][wn + j * 16 + b_row_off][ks + b_col_off]);
            #pragma unroll
            for (int mi = 0; mi < 4; mi++)
                #pragma unroll
                for (int ni = 0; ni < 4; ni++)
                    asm volatile(
                        "mma.sync.aligned.m16n8k16.row.col.f32.f16.f16.f32 "
                        "{%0,%1,%2,%3}, {%4,%5,%6,%7}, {%8,%9}, {%0,%1,%2,%3};\n"
                        : "+f"(acc[mi][ni][0]), "+f"(acc[mi][ni][1]),
                          "+f"(acc[mi][ni][2]), "+f"(acc[mi][ni][3])
                        : "r"(af[mi][0]), "r"(af[mi][1]), "r"(af[mi][2]), "r"(af[mi][3]),
                          "r"(bf[ni][0]), "r"(bf[ni][1]));
        }
        __syncthreads();
        buf ^= 1;
    }

    #pragma unroll
    for (int mi = 0; mi < 4; mi++) {
        int row = bM + wm + mi * 16 + g;
        #pragma unroll
        for (int ni = 0; ni < 4; ni++) {
            int col = bN + wn + ni * 8 + t4 * 2;
            if (HALF_OUT) {
                *(__half2*)&Ch[(long)row * N + col] =
                    __floats2half2_rn(acc[mi][ni][0], acc[mi][ni][1]);
                *(__half2*)&Ch[(long)(row + 8) * N + col] =
                    __floats2half2_rn(acc[mi][ni][2], acc[mi][ni][3]);
            } else {
                float b0 = bias[col], b1 = bias[col + 1];
                float2 v0 = make_float2(acc[mi][ni][0] + b0, acc[mi][ni][1] + b1);
                float2 v1 = make_float2(acc[mi][ni][2] + b0, acc[mi][ni][3] + b1);
                *(float2*)&Cf[(long)row * N + col] = v0;
                *(float2*)&Cf[(long)(row + 8) * N + col] = v1;
            }
        }
    }
}

// ---------------- middle stage: per-batch Linformer attention ----------------
// qkv row layout: g_qkv[(b*4+n)*3072 + s*1024 + h*64 + d], s=0:q 1:k 2:v
__device__ __forceinline__ float dot64_vec(const __half* __restrict__ a,
                                           const __half* __restrict__ b) {
    // 64-element dot product via 8x uint4 (8 halves each), fp32 accumulate
    float s = 0.f;
    #pragma unroll
    for (int j = 0; j < 8; j++) {
        uint4 va = *(const uint4*)(a + j * 8);
        uint4 vb = *(const uint4*)(b + j * 8);
        const __half2* ha = (const __half2*)&va;
        const __half2* hb = (const __half2*)&vb;
        #pragma unroll
        for (int q = 0; q < 4; q++) {
            float2 fa = __half22float2(ha[q]);
            float2 fb = __half22float2(hb[q]);
            s += fa.x * fb.x + fa.y * fb.y;
        }
    }
    return s;
}

__global__ __launch_bounds__(128) void mid_kernel(
    const __half* __restrict__ qkv_all, __half* __restrict__ y,
    const float* __restrict__ W_E, const float* __restrict__ W_F,
    float* __restrict__ attn_out)
{
    __shared__ __half buf[4 * 1024];          // one of {k, v} staged
    __shared__ float klow[16][4][64];
    __shared__ float vlow[16][4][64];
    __shared__ float wE[4][4], wF[4][4];

    const int b = blockIdx.x, t = threadIdx.x;
    const __half* qkv = qkv_all + (long)b * 4 * 3072;

    if (t < 16) { wE[t >> 2][t & 3] = W_E[t]; wF[t >> 2][t & 3] = W_F[t]; }

    // stage K rows (s=1)
    for (int i = t; i < 512; i += 128) {
        int n = i >> 7, c8 = (i & 127) << 3;
        *(uint4*)&buf[n * 1024 + c8] = *(const uint4*)&qkv[n * 3072 + 1024 + c8];
    }
    __syncthreads();

    // klow[h][p][d] = sum_n wE[p][n] * k[n][h*64+d]
    for (int i = t; i < 1024; i += 128) {
        int h = i >> 6, d = i & 63, c = h * 64 + d;
        float k0 = __half2float(buf[c]);
        float k1 = __half2float(buf[1024 + c]);
        float k2 = __half2float(buf[2048 + c]);
        float k3 = __half2float(buf[3072 + c]);
        #pragma unroll
        for (int p = 0; p < 4; p++)
            klow[h][p][d] = wE[p][0] * k0 + wE[p][1] * k1 + wE[p][2] * k2 + wE[p][3] * k3;
    }

    // attn_sel_sig[h][g] = sigmoid( SCALE * q[n=1,h,:] . k[n=2,g,:] ) — vectorized
    for (int i = t; i < 256; i += 128) {
        int h = i >> 4, gg = i & 15;
        float s = dot64_vec(qkv + 1 * 3072 + h * 64, &buf[2048 + gg * 64]) * SCALE_F;
        attn_out[b * 256 + i] = 1.f / (1.f + expf(-s));
    }
    __syncthreads();

    // stage V rows (s=2)
    for (int i = t; i < 512; i += 128) {
        int n = i >> 7, c8 = (i & 127) << 3;
        *(uint4*)&buf[n * 1024 + c8] = *(const uint4*)&qkv[n * 3072 + 2048 + c8];
    }
    __syncthreads();

    for (int i = t; i < 1024; i += 128) {
        int h = i >> 6, d = i & 63, c = h * 64 + d;
        float v0 = __half2float(buf[c]);
        float v1 = __half2float(buf[1024 + c]);
        float v2 = __half2float(buf[2048 + c]);
        float v3 = __half2float(buf[3072 + c]);
        #pragma unroll
        for (int p = 0; p < 4; p++)
            vlow[h][p][d] = wF[p][0] * v0 + wF[p][1] * v1 + wF[p][2] * v2 + wF[p][3] * v3;
    }
    __syncthreads();

    // attn softmax over P=4 and Y = attn @ vlow (q loads vectorized)
    if (t < 64) {
        int h = t >> 2, n = t & 3;
        const __half* qrow = qkv + n * 3072 + h * 64;
        float qv[64];
        #pragma unroll
        for (int j = 0; j < 8; j++) {
            uint4 vq = *(const uint4*)(qrow + j * 8);
            const __half2* hq = (const __half2*)&vq;
            #pragma unroll
            for (int q = 0; q < 4; q++) {
                float2 f = __half22float2(hq[q]);
                qv[j * 8 + q * 2]     = f.x;
                qv[j * 8 + q * 2 + 1] = f.y;
            }
        }
        float l0 = 0, l1 = 0, l2 = 0, l3 = 0;
        #pragma unroll
        for (int d = 0; d < 64; d++) {
            l0 += qv[d] * klow[h][0][d];
            l1 += qv[d] * klow[h][1][d];
            l2 += qv[d] * klow[h][2][d];
            l3 += qv[d] * klow[h][3][d];
        }
        l0 *= SCALE_F; l1 *= SCALE_F; l2 *= SCALE_F; l3 *= SCALE_F;
        float m = fmaxf(fmaxf(l0, l1), fmaxf(l2, l3));
        float e0 = expf(l0 - m), e1 = expf(l1 - m), e2 = expf(l2 - m), e3 = expf(l3 - m);
        float inv = 1.f / (e0 + e1 + e2 + e3);
        e0 *= inv; e1 *= inv; e2 *= inv; e3 *= inv;
        __half* yrow = y + (long)(b * 4 + n) * 1024 + h * 64;
        #pragma unroll
        for (int d = 0; d < 64; d += 2) {
            float o0 = e0 * vlow[h][0][d] + e1 * vlow[h][1][d] + e2 * vlow[h][2][d] + e3 * vlow[h][3][d];
            float o1 = e0 * vlow[h][0][d + 1] + e1 * vlow[h][1][d + 1] + e2 * vlow[h][2][d + 1] + e3 * vlow[h][3][d + 1];
            *(__half2*)&yrow[d] = __floats2half2_rn(o0, o1);
        }
    }
}

// ---------------- launch -----------------------------------------------------
extern "C" void kernel_launch(void* const* d_in, const int* in_sizes, int n_in,
                              void* d_out, int out_size)
{
    const float* x     = (const float*)d_in[0];
    const float* Wqkv  = (const float*)d_in[1];
    const float* Wproj = (const float*)d_in[2];
    const float* bproj = (const float*)d_in[3];
    const float* WE    = (const float*)d_in[4];
    const float* WF    = (const float*)d_in[5];
    float* out = (float*)d_out;

    void *p_xh, *p_wq, *p_wp, *p_qkv, *p_y;
    cudaGetSymbolAddress(&p_xh,  g_xh);
    cudaGetSymbolAddress(&p_wq,  g_wqkvT);
    cudaGetSymbolAddress(&p_wp,  g_wprojh);
    cudaGetSymbolAddress(&p_qkv, g_qkv);
    cudaGetSymbolAddress(&p_y,   g_y);
    const __half* xh   = (const __half*)p_xh;
    const __half* wqT  = (const __half*)p_wq;
    const __half* wph  = (const __half*)p_wp;
    __half* qkv = (__half*)p_qkv;
    __half* y   = (__half*)p_y;

    // converts
    cvt_x_kernel<<<MTOK * CC / 4 / 256, 256>>>(x);
    cvt_wqkv_kernel<<<dim3(96, 32), dim3(32, 8)>>>(Wqkv);
    cvt_wproj_kernel<<<CC * CC / 256, 256>>>(Wproj);

    // GEMM1: qkv = x @ W_qkv   (M=32768, N=3072, K=1024) -> half
    gemm_kernel<true><<<dim3(3072 / 128, MTOK / 128), 256>>>(
        xh, wqT, qkv, nullptr, nullptr, 3072, 1024);

    // middle attention per batch
    mid_kernel<<<BB, 128>>>(qkv, y, WE, WF, out + (long)MTOK * CC);

    // GEMM2: out = Y @ W_proj^T + b   (M=32768, N=1024, K=1024) -> fp32 into d_out
    gemm_kernel<false><<<dim3(1024 / 128, MTOK / 128), 256>>>(
        y, wph, nullptr, out, bproj, 1024, 1024);
}